// round 7
// baseline (speedup 1.0000x reference)
#include <cuda_runtime.h>
#include <cuda_bf16.h>
#include <math.h>

#define N_ROWS 4096
#define V_SIZE 50000
#define D_DIM  300
#define DP     304
#define BM     64
#define BN     64
#define SPLITS 7
#define VC     7168   // vocab rows per split (112 tiles of 64); last split = 6992

// ---------------- scratch (device globals; no allocation allowed) ----------------
__device__ float g_wp  [N_ROWS * D_DIM];            // words @ W
__device__ float g_pacc[SPLITS * N_ROWS * DP];      // per-split unnormalized sum_j e^{s-m} v_j
__device__ float g_pm  [SPLITS * N_ROWS];           // per-split running max
__device__ float g_pl  [SPLITS * N_ROWS];           // per-split running sum of exp

// ---------------- fast exp (FFMA pipe instead of MUFU) ----------------
// exp(x) for x <= 0 (clamped). rel err ~2e-6.
__device__ __forceinline__ float fexp(float x) {
    float p = x * 1.4426950408889634f;     // log2(e)
    p = fmaxf(p, -120.0f);                 // 2^-120 ~ 0; also guards -1e30 masks
    float fn = rintf(p);
    float f  = p - fn;                     // f in [-0.5, 0.5]
    // degree-5 Taylor of 2^f
    float y = 1.3333558146e-3f;
    y = fmaf(y, f, 9.6181291076e-3f);
    y = fmaf(y, f, 5.5504108664e-2f);
    y = fmaf(y, f, 2.4022650695e-1f);
    y = fmaf(y, f, 6.9314718055e-1f);
    y = fmaf(y, f, 1.0f);
    int e = (int)fn;
    float s = __int_as_float((e + 127) << 23);
    return y * s;
}

// ---------------- kernel 1: wp = words @ W ----------------
__global__ __launch_bounds__(320)
void gemm1_kernel(const float* __restrict__ words, const float* __restrict__ W) {
    __shared__ float ws[16 * D_DIM];
    int i0 = blockIdx.x * 16;
    int tid = threadIdx.x;
    for (int t = tid; t < 16 * D_DIM; t += 320)
        ws[t] = words[i0 * D_DIM + t];
    __syncthreads();
    int d = tid;
    if (d < D_DIM) {
        float acc[16];
        #pragma unroll
        for (int r = 0; r < 16; ++r) acc[r] = 0.f;
        for (int k4 = 0; k4 < D_DIM / 4; ++k4) {
            int k = k4 * 4;
            float w0 = W[(k + 0) * D_DIM + d];
            float w1 = W[(k + 1) * D_DIM + d];
            float w2 = W[(k + 2) * D_DIM + d];
            float w3 = W[(k + 3) * D_DIM + d];
            #pragma unroll
            for (int r = 0; r < 16; ++r) {
                float4 wv = *(const float4*)&ws[r * D_DIM + k];
                acc[r] = fmaf(wv.x, w0, acc[r]);
                acc[r] = fmaf(wv.y, w1, acc[r]);
                acc[r] = fmaf(wv.z, w2, acc[r]);
                acc[r] = fmaf(wv.w, w3, acc[r]);
            }
        }
        #pragma unroll
        for (int r = 0; r < 16; ++r)
            g_wp[(i0 + r) * D_DIM + d] = acc[r];
    }
}

// ---------------- kernel 2: fused flash scores+softmax+value ----------------
// smem floats: wp_sT[300][64] | v_s[64][304] | vT_s[64][68] (reused as S_s) |
//              p_sT[64][68] | m_s[64] l_s[64] al_s[64]
#define SMEM_FLOATS (300*64 + 64*DP + 64*68 + 64*68 + 192)
#define SMEM_BYTES  (SMEM_FLOATS * 4)

__global__ __launch_bounds__(256, 1)
void fused_kernel(const float* __restrict__ vocab) {
    extern __shared__ float sm[];
    float* wp_sT = sm;                       // [300][64]  K-major wp tile
    float* v_s   = wp_sT + 300 * 64;         // [64][304]  row-major vocab tile (value layout)
    float* vT_s  = v_s + 64 * DP;            // [64][68]   K-chunk of vocab transposed; reused as S tile
    float* p_sT  = vT_s + 64 * 68;           // [64][68]   p transposed [j][i]
    float* m_s   = p_sT + 64 * 68;
    float* l_s   = m_s + 64;
    float* al_s  = l_s + 64;

    const int tid    = threadIdx.x;
    const int row0   = blockIdx.x * BM;
    const int split  = blockIdx.y;
    const int jbeg   = split * VC;
    const int jend   = min(V_SIZE, jbeg + VC);
    const int ntiles = (jend - jbeg + BN - 1) / BN;

    // score-GEMM mapping: 4 K-groups x 64 positions (8x8 microtile)
    const int kg  = tid >> 6;
    const int pos = tid & 63;
    const int sty = pos >> 3;   // rows sty*8 .. +7
    const int stx = pos & 7;    // cols stx*8 .. +7
    // value-GEMM mapping: 8 row groups x 32 d-lanes
    const int rg = tid >> 5;    // rows rg*8 .. +7
    const int dc = tid & 31;    // d chunks: dc*4, 128+dc*4, 256+dc*4 (last if dc<12)
    const bool c2ok = (dc < 12);

    // load wp tile transposed into smem (one-time; LDG uncoalesced but tiny vs mainloop)
    for (int t = tid; t < BM * D_DIM; t += 256) {
        int i = t & 63;
        int d = t >> 6;
        wp_sT[d * 64 + i] = g_wp[(row0 + i) * D_DIM + d];
    }
    if (tid < 64) { m_s[tid] = -1e30f; l_s[tid] = 0.f; al_s[tid] = 1.f; }

    float o[8][12];
    #pragma unroll
    for (int r = 0; r < 8; ++r)
        #pragma unroll
        for (int c = 0; c < 12; ++c) o[r][c] = 0.f;

    __syncthreads();

    for (int tile = 0; tile < ntiles; ++tile) {
        const int j0    = jbeg + tile * BN;
        const int valid = min(BN, jend - j0);

        // ---- A: load vocab tile (row-major, zero-padded cols 300..303 and OOB rows)
        for (int t = tid; t < 64 * 76; t += 256) {
            int j = t / 76;
            int c = t - j * 76;
            float4 val = make_float4(0.f, 0.f, 0.f, 0.f);
            if (j < valid && c < 75)
                val = ((const float4*)vocab)[(j0 + j) * 75 + c];
            ((float4*)v_s)[j * 76 + c] = val;
        }
        __syncthreads();

        // ---- B: score GEMM, 5 K-chunks with smem transpose staging
        float sc[8][8];
        #pragma unroll
        for (int r = 0; r < 8; ++r)
            #pragma unroll
            for (int c = 0; c < 8; ++c) sc[r][c] = 0.f;

        for (int ch = 0; ch < 5; ++ch) {
            const int kbase = ch * 64;
            const int klen  = (ch < 4) ? 64 : (D_DIM - 256);  // 44
            for (int t = tid; t < 64 * 64; t += 256) {
                int kk = t & 63;
                int j  = t >> 6;
                if (kk < klen) vT_s[kk * 68 + j] = v_s[j * DP + kbase + kk];
            }
            __syncthreads();
            for (int kk = kg; kk < klen; kk += 4) {
                float4 a0 = *(const float4*)&wp_sT[(kbase + kk) * 64 + sty * 8];
                float4 a1 = *(const float4*)&wp_sT[(kbase + kk) * 64 + sty * 8 + 4];
                float4 b0 = *(const float4*)&vT_s[kk * 68 + stx * 8];
                float4 b1 = *(const float4*)&vT_s[kk * 68 + stx * 8 + 4];
                float a[8] = {a0.x, a0.y, a0.z, a0.w, a1.x, a1.y, a1.z, a1.w};
                float b[8] = {b0.x, b0.y, b0.z, b0.w, b1.x, b1.y, b1.z, b1.w};
                #pragma unroll
                for (int r = 0; r < 8; ++r)
                    #pragma unroll
                    for (int c = 0; c < 8; ++c)
                        sc[r][c] = fmaf(a[r], b[c], sc[r][c]);
            }
            __syncthreads();
        }

        // ---- C: reduce 4 K-group partials into S_s (reuse vT_s memory)
        float* S_s = vT_s;
        #pragma unroll 1
        for (int g = 0; g < 4; ++g) {
            if (kg == g) {
                #pragma unroll
                for (int r = 0; r < 8; ++r) {
                    float* dst = &S_s[(sty * 8 + r) * 68 + stx * 8];
                    if (g == 0) {
                        ((float4*)dst)[0] = make_float4(sc[r][0], sc[r][1], sc[r][2], sc[r][3]);
                        ((float4*)dst)[1] = make_float4(sc[r][4], sc[r][5], sc[r][6], sc[r][7]);
                    } else {
                        float4 x0 = ((float4*)dst)[0];
                        float4 x1 = ((float4*)dst)[1];
                        x0.x += sc[r][0]; x0.y += sc[r][1]; x0.z += sc[r][2]; x0.w += sc[r][3];
                        x1.x += sc[r][4]; x1.y += sc[r][5]; x1.z += sc[r][6]; x1.w += sc[r][7];
                        ((float4*)dst)[0] = x0;
                        ((float4*)dst)[1] = x1;
                    }
                }
            }
            __syncthreads();
        }

        // ---- D: online softmax update (4 threads per row)
        {
            const int row = tid >> 2;
            const int q   = tid & 3;
            float sv[16];
            float mloc = -1e30f;
            #pragma unroll
            for (int c = 0; c < 16; ++c) {
                int j = q * 16 + c;
                float s = S_s[row * 68 + j];
                if (j >= valid) s = -1e30f;
                sv[c] = s;
                mloc = fmaxf(mloc, s);
            }
            #pragma unroll
            for (int off = 1; off < 4; off <<= 1)
                mloc = fmaxf(mloc, __shfl_xor_sync(0xffffffffu, mloc, off));
            const float mold = m_s[row];
            const float mnew = fmaxf(mold, mloc);
            float rs = 0.f;
            #pragma unroll
            for (int c = 0; c < 16; ++c) {
                float p = fexp(sv[c] - mnew);   // masked entries -> ~2^-120 ~ 0
                p_sT[(q * 16 + c) * 68 + row] = p;
                rs += p;
            }
            #pragma unroll
            for (int off = 1; off < 4; off <<= 1)
                rs += __shfl_xor_sync(0xffffffffu, rs, off);
            if (q == 0) {
                float alpha = fexp(mold - mnew);
                l_s[row]  = l_s[row] * alpha + rs;
                m_s[row]  = mnew;
                al_s[row] = alpha;
            }
        }
        __syncthreads();

        // ---- E: value GEMM accumulate (rescale then += P @ V_tile)
        {
            float av[8];
            #pragma unroll
            for (int r = 0; r < 8; ++r) av[r] = al_s[rg * 8 + r];
            #pragma unroll
            for (int r = 0; r < 8; ++r)
                #pragma unroll
                for (int c = 0; c < 12; ++c) o[r][c] *= av[r];

            #pragma unroll 2
            for (int j = 0; j < 64; ++j) {
                float4 p0 = *(const float4*)&p_sT[j * 68 + rg * 8];
                float4 p1 = *(const float4*)&p_sT[j * 68 + rg * 8 + 4];
                float pr[8] = {p0.x, p0.y, p0.z, p0.w, p1.x, p1.y, p1.z, p1.w};
                float4 v0 = *(const float4*)&v_s[j * DP + dc * 4];
                float4 v1 = *(const float4*)&v_s[j * DP + 128 + dc * 4];
                float4 v2 = c2ok ? *(const float4*)&v_s[j * DP + 256 + dc * 4]
                                 : make_float4(0.f, 0.f, 0.f, 0.f);
                float vv[12] = {v0.x, v0.y, v0.z, v0.w,
                                v1.x, v1.y, v1.z, v1.w,
                                v2.x, v2.y, v2.z, v2.w};
                #pragma unroll
                for (int r = 0; r < 8; ++r)
                    #pragma unroll
                    for (int c = 0; c < 12; ++c)
                        o[r][c] = fmaf(pr[r], vv[c], o[r][c]);
            }
        }
        __syncthreads();
    }

    // ---- F: write split partials
    {
        const int base = split * N_ROWS + row0;
        #pragma unroll
        for (int r = 0; r < 8; ++r) {
            float* dst = &g_pacc[(base + rg * 8 + r) * DP];
            *(float4*)(dst + dc * 4)       = make_float4(o[r][0], o[r][1], o[r][2],  o[r][3]);
            *(float4*)(dst + 128 + dc * 4) = make_float4(o[r][4], o[r][5], o[r][6],  o[r][7]);
            if (c2ok)
                *(float4*)(dst + 256 + dc * 4) = make_float4(o[r][8], o[r][9], o[r][10], o[r][11]);
        }
        if (tid < 64) {
            g_pm[split * N_ROWS + row0 + tid] = m_s[tid];
            g_pl[split * N_ROWS + row0 + tid] = l_s[tid];
        }
    }
}

// ---------------- kernel 3: combine splits + default-embed column ----------------
__global__ __launch_bounds__(320)
void combine_kernel(const float* __restrict__ words,
                    const float* __restrict__ defv,
                    float* __restrict__ out) {
    const int i   = blockIdx.x;
    const int tid = threadIdx.x;
    __shared__ float red[10];
    __shared__ float sdef_sh;

    // s_def = wp[i] . default_embed
    float prod = 0.f;
    if (tid < D_DIM) prod = g_wp[i * D_DIM + tid] * defv[tid];
    #pragma unroll
    for (int off = 16; off > 0; off >>= 1)
        prod += __shfl_xor_sync(0xffffffffu, prod, off);
    if ((tid & 31) == 0) red[tid >> 5] = prod;
    __syncthreads();
    if (tid == 0) {
        float s = 0.f;
        #pragma unroll
        for (int w = 0; w < 10; ++w) s += red[w];
        sdef_sh = s;
    }
    __syncthreads();
    const float sdef = sdef_sh;

    float m[SPLITS], l[SPLITS];
    float M = sdef;
    #pragma unroll
    for (int s = 0; s < SPLITS; ++s) {
        m[s] = g_pm[s * N_ROWS + i];
        l[s] = g_pl[s * N_ROWS + i];
        M = fmaxf(M, m[s]);
    }
    float w[SPLITS];
    float edef = fexp(sdef - M);
    float L = edef;
    #pragma unroll
    for (int s = 0; s < SPLITS; ++s) {
        w[s] = fexp(m[s] - M);
        L += l[s] * w[s];
    }
    const float inv = 1.f / L;
    if (tid < D_DIM) {
        float acc = 0.f;
        #pragma unroll
        for (int s = 0; s < SPLITS; ++s)
            acc += g_pacc[(s * N_ROWS + i) * DP + tid] * w[s];
        out[i * D_DIM + tid] = acc * inv + (edef * inv) * words[i * D_DIM + tid];
    }
}

// ---------------- launcher ----------------
extern "C" void kernel_launch(void* const* d_in, const int* in_sizes, int n_in,
                              void* d_out, int out_size) {
    const float* words = (const float*)d_in[0];   // [4096, 300]
    const float* vocab = (const float*)d_in[1];   // [50000, 300]
    const float* defv  = (const float*)d_in[2];   // [300]
    const float* W     = (const float*)d_in[3];   // [300, 300]
    float* out = (float*)d_out;                   // [4096, 300]

    cudaFuncSetAttribute(fused_kernel,
                         cudaFuncAttributeMaxDynamicSharedMemorySize, SMEM_BYTES);

    gemm1_kernel<<<N_ROWS / 16, 320>>>(words, W);
    fused_kernel<<<dim3(N_ROWS / BM, SPLITS), 256, SMEM_BYTES>>>(vocab);
    combine_kernel<<<N_ROWS, 320>>>(words, defv, out);
}

// round 8
// speedup vs baseline: 1.1350x; 1.1350x over previous
#include <cuda_runtime.h>
#include <cuda_bf16.h>
#include <math.h>

#define N_ROWS 4096
#define V_SIZE 50000
#define D_DIM  300
#define DP     320    // padded d stride (floats) for value GEMM / g_pacc
#define BM     64
#define BN     64
#define SPLITS 16
#define VC     3136   // vocab rows per split (49 tiles of 64); last split = 2960

typedef unsigned long long u64;

// ---------------- packed f32x2 helpers ----------------
__device__ __forceinline__ u64 pack2(float lo, float hi) {
    u64 r; asm("mov.b64 %0, {%1, %2};" : "=l"(r) : "f"(lo), "f"(hi)); return r;
}
__device__ __forceinline__ u64 fma2(u64 a, u64 b, u64 c) {
    u64 d; asm("fma.rn.f32x2 %0, %1, %2, %3;" : "=l"(d) : "l"(a), "l"(b), "l"(c)); return d;
}
__device__ __forceinline__ u64 add2(u64 a, u64 b) {
    u64 d; asm("add.rn.f32x2 %0, %1, %2;" : "=l"(d) : "l"(a), "l"(b)); return d;
}
__device__ __forceinline__ u64 mul2(u64 a, u64 b) {
    u64 d; asm("mul.rn.f32x2 %0, %1, %2;" : "=l"(d) : "l"(a), "l"(b)); return d;
}

// ---------------- scratch (device globals; no allocation allowed) ----------------
__device__ float g_wp  [N_ROWS * D_DIM];            // words @ W
__device__ float g_pacc[SPLITS * N_ROWS * DP];      // per-split unnormalized sum_j e^{s-m} v_j
__device__ float g_pm  [SPLITS * N_ROWS];           // per-split running max
__device__ float g_pl  [SPLITS * N_ROWS];           // per-split running sum of exp

// ---------------- fast exp (FFMA pipe instead of MUFU) ----------------
__device__ __forceinline__ float fexp(float x) {
    float p = x * 1.4426950408889634f;     // log2(e)
    p = fmaxf(p, -120.0f);                 // 2^-120 ~ 0; also guards -1e30 masks
    float fn = rintf(p);
    float f  = p - fn;                     // f in [-0.5, 0.5]
    float y = 1.3333558146e-3f;
    y = fmaf(y, f, 9.6181291076e-3f);
    y = fmaf(y, f, 5.5504108664e-2f);
    y = fmaf(y, f, 2.4022650695e-1f);
    y = fmaf(y, f, 6.9314718055e-1f);
    y = fmaf(y, f, 1.0f);
    int e = (int)fn;
    float s = __int_as_float((e + 127) << 23);
    return y * s;
}

// ---------------- kernel 1: wp = words @ W ----------------
__global__ __launch_bounds__(320)
void gemm1_kernel(const float* __restrict__ words, const float* __restrict__ W) {
    __shared__ float ws[16 * D_DIM];
    int i0 = blockIdx.x * 16;
    int tid = threadIdx.x;
    for (int t = tid; t < 16 * D_DIM; t += 320)
        ws[t] = words[i0 * D_DIM + t];
    __syncthreads();
    int d = tid;
    if (d < D_DIM) {
        float acc[16];
        #pragma unroll
        for (int r = 0; r < 16; ++r) acc[r] = 0.f;
        for (int k4 = 0; k4 < D_DIM / 4; ++k4) {
            int k = k4 * 4;
            float w0 = W[(k + 0) * D_DIM + d];
            float w1 = W[(k + 1) * D_DIM + d];
            float w2 = W[(k + 2) * D_DIM + d];
            float w3 = W[(k + 3) * D_DIM + d];
            #pragma unroll
            for (int r = 0; r < 16; ++r) {
                float4 wv = *(const float4*)&ws[r * D_DIM + k];
                acc[r] = fmaf(wv.x, w0, acc[r]);
                acc[r] = fmaf(wv.y, w1, acc[r]);
                acc[r] = fmaf(wv.z, w2, acc[r]);
                acc[r] = fmaf(wv.w, w3, acc[r]);
            }
        }
        #pragma unroll
        for (int r = 0; r < 16; ++r)
            g_wp[(i0 + r) * D_DIM + d] = acc[r];
    }
}

// ---------------- kernel 2: fused flash scores+softmax+value (FFMA2) ----------------
// smem floats:
//   wp_sT [300][64]        19200
//   v_s   [64][320]        20480   (row-major vocab tile, zero-padded 300..319)
//   vT_s  [64][68]          4352   (K-chunk transpose; reused as S tile)
//   p2    [64][68] u64      8704   (pre-duplicated (p,p) pairs, [j][i])
//   m/l/al 3*64              192
#define OFF_WP   0
#define OFF_V    (OFF_WP + 300*64)
#define OFF_VT   (OFF_V  + 64*DP)
#define OFF_P2   (OFF_VT + 64*68)        // in floats; u64 region of 64*68 u64
#define OFF_MLA  (OFF_P2 + 64*68*2)
#define SMEM_FLOATS (OFF_MLA + 192)
#define SMEM_BYTES  (SMEM_FLOATS * 4)

__global__ __launch_bounds__(256, 1)
void fused_kernel(const float* __restrict__ vocab) {
    extern __shared__ float sm[];
    float* wp_sT = sm + OFF_WP;
    float* v_s   = sm + OFF_V;
    float* vT_s  = sm + OFF_VT;
    u64*   p2    = (u64*)(sm + OFF_P2);
    float* m_s   = sm + OFF_MLA;
    float* l_s   = m_s + 64;
    float* al_s  = l_s + 64;

    const int tid    = threadIdx.x;
    const int row0   = blockIdx.x * BM;
    const int split  = blockIdx.y;
    const int jbeg   = split * VC;
    const int jend   = min(V_SIZE, jbeg + VC);
    const int ntiles = (jend - jbeg + BN - 1) / BN;

    // score-GEMM mapping: 4 K-groups x 64 positions (8x8 microtile)
    const int kg  = tid >> 6;
    const int pos = tid & 63;
    const int sty = pos >> 3;   // rows sty*8 .. +7
    const int stx = pos & 7;    // cols stx*8 .. +7
    // value-GEMM mapping: 8 row groups x 32 d-lanes, 5 float2 chunks per lane
    const int rg = tid >> 5;    // rows rg*8 .. +7
    const int dc = tid & 31;    // float2 pairs at 2*dc + 64*c, c=0..4 (covers 320 floats)

    // one-time wp tile load (transposed, K-major)
    for (int t = tid; t < BM * D_DIM; t += 256) {
        int i = t & 63;
        int d = t >> 6;
        wp_sT[d * 64 + i] = g_wp[(row0 + i) * D_DIM + d];
    }
    if (tid < 64) { m_s[tid] = -1e30f; l_s[tid] = 0.f; al_s[tid] = 1.f; }

    u64 o2[8][5];
    #pragma unroll
    for (int r = 0; r < 8; ++r)
        #pragma unroll
        for (int c = 0; c < 5; ++c) o2[r][c] = 0ull;

    __syncthreads();

    for (int tile = 0; tile < ntiles; ++tile) {
        const int j0    = jbeg + tile * BN;
        const int valid = min(BN, jend - j0);

        // ---- A: load vocab tile (row-major, zero-padded cols 300..319, OOB rows)
        for (int t = tid; t < 64 * (DP / 4); t += 256) {
            int j = t / (DP / 4);
            int c = t - j * (DP / 4);
            float4 val = make_float4(0.f, 0.f, 0.f, 0.f);
            if (j < valid && c < 75)
                val = ((const float4*)vocab)[(j0 + j) * 75 + c];
            ((float4*)v_s)[j * (DP / 4) + c] = val;
        }
        __syncthreads();

        // ---- B: score GEMM (packed f32x2 along columns), 5 K-chunks w/ transpose staging
        u64 sc2[8][4];
        #pragma unroll
        for (int r = 0; r < 8; ++r)
            #pragma unroll
            for (int c = 0; c < 4; ++c) sc2[r][c] = 0ull;

        for (int ch = 0; ch < 5; ++ch) {
            const int kbase = ch * 64;
            const int klen  = (ch < 4) ? 64 : (D_DIM - 256);  // 44
            for (int t = tid; t < 64 * 64; t += 256) {
                int kk = t & 63;
                int j  = t >> 6;
                if (kk < klen) vT_s[kk * 68 + j] = v_s[j * DP + kbase + kk];
            }
            __syncthreads();
            for (int kk = kg; kk < klen; kk += 4) {
                float4 a0 = *(const float4*)&wp_sT[(kbase + kk) * 64 + sty * 8];
                float4 a1 = *(const float4*)&wp_sT[(kbase + kk) * 64 + sty * 8 + 4];
                float4 b0 = *(const float4*)&vT_s[kk * 68 + stx * 8];
                float4 b1 = *(const float4*)&vT_s[kk * 68 + stx * 8 + 4];
                union { float4 f; u64 u[2]; } ub0, ub1;
                ub0.f = b0; ub1.f = b1;
                u64 bp[4] = {ub0.u[0], ub0.u[1], ub1.u[0], ub1.u[1]};
                float a[8] = {a0.x, a0.y, a0.z, a0.w, a1.x, a1.y, a1.z, a1.w};
                #pragma unroll
                for (int r = 0; r < 8; ++r) {
                    u64 ar = pack2(a[r], a[r]);
                    #pragma unroll
                    for (int c = 0; c < 4; ++c)
                        sc2[r][c] = fma2(ar, bp[c], sc2[r][c]);
                }
            }
            __syncthreads();
        }

        // ---- C: reduce 4 K-group partials into S tile (reuse vT_s), packed adds
        u64* S2 = (u64*)vT_s;   // stride 34 u64 per row
        #pragma unroll 1
        for (int g = 0; g < 4; ++g) {
            if (kg == g) {
                #pragma unroll
                for (int r = 0; r < 8; ++r) {
                    u64* dst = &S2[(sty * 8 + r) * 34 + stx * 4];
                    if (g == 0) {
                        #pragma unroll
                        for (int c = 0; c < 4; ++c) dst[c] = sc2[r][c];
                    } else {
                        #pragma unroll
                        for (int c = 0; c < 4; ++c) dst[c] = add2(dst[c], sc2[r][c]);
                    }
                }
            }
            __syncthreads();
        }

        // ---- D: online softmax update (4 threads per row); store (p,p) pairs
        {
            float* S_s = vT_s;
            const int row = tid >> 2;
            const int q   = tid & 3;
            float sv[16];
            float mloc = -1e30f;
            #pragma unroll
            for (int c = 0; c < 16; ++c) {
                int j = q * 16 + c;
                float s = S_s[row * 68 + j];
                if (j >= valid) s = -1e30f;
                sv[c] = s;
                mloc = fmaxf(mloc, s);
            }
            #pragma unroll
            for (int off = 1; off < 4; off <<= 1)
                mloc = fmaxf(mloc, __shfl_xor_sync(0xffffffffu, mloc, off));
            const float mold = m_s[row];
            const float mnew = fmaxf(mold, mloc);
            float rs = 0.f;
            #pragma unroll
            for (int c = 0; c < 16; ++c) {
                float p = fexp(sv[c] - mnew);
                p2[(q * 16 + c) * 68 + row] = pack2(p, p);
                rs += p;
            }
            #pragma unroll
            for (int off = 1; off < 4; off <<= 1)
                rs += __shfl_xor_sync(0xffffffffu, rs, off);
            if (q == 0) {
                float alpha = fexp(mold - mnew);
                l_s[row]  = l_s[row] * alpha + rs;
                m_s[row]  = mnew;
                al_s[row] = alpha;
            }
        }
        __syncthreads();

        // ---- E: value GEMM accumulate (packed f32x2; rescale then += P @ V_tile)
        {
            #pragma unroll
            for (int r = 0; r < 8; ++r) {
                u64 av = pack2(al_s[rg * 8 + r], al_s[rg * 8 + r]);
                #pragma unroll
                for (int c = 0; c < 5; ++c) o2[r][c] = mul2(o2[r][c], av);
            }

            #pragma unroll 2
            for (int j = 0; j < 64; ++j) {
                const u64* pj = &p2[j * 68 + rg * 8];
                ulonglong2 pA = *(const ulonglong2*)(pj + 0);
                ulonglong2 pB = *(const ulonglong2*)(pj + 2);
                ulonglong2 pC = *(const ulonglong2*)(pj + 4);
                ulonglong2 pD = *(const ulonglong2*)(pj + 6);
                u64 pr[8] = {pA.x, pA.y, pB.x, pB.y, pC.x, pC.y, pD.x, pD.y};
                u64 vv[5];
                #pragma unroll
                for (int c = 0; c < 5; ++c)
                    vv[c] = *(const u64*)&v_s[j * DP + 2 * dc + 64 * c];
                #pragma unroll
                for (int r = 0; r < 8; ++r)
                    #pragma unroll
                    for (int c = 0; c < 5; ++c)
                        o2[r][c] = fma2(pr[r], vv[c], o2[r][c]);
            }
        }
        __syncthreads();
    }

    // ---- F: write split partials (packed stores)
    {
        const int base = split * N_ROWS + row0;
        #pragma unroll
        for (int r = 0; r < 8; ++r) {
            float* dst = &g_pacc[(size_t)(base + rg * 8 + r) * DP];
            #pragma unroll
            for (int c = 0; c < 5; ++c)
                *(u64*)&dst[2 * dc + 64 * c] = o2[r][c];
        }
        if (tid < 64) {
            g_pm[split * N_ROWS + row0 + tid] = m_s[tid];
            g_pl[split * N_ROWS + row0 + tid] = l_s[tid];
        }
    }
}

// ---------------- kernel 3: combine splits + default-embed column ----------------
__global__ __launch_bounds__(320)
void combine_kernel(const float* __restrict__ words,
                    const float* __restrict__ defv,
                    float* __restrict__ out) {
    const int i   = blockIdx.x;
    const int tid = threadIdx.x;
    __shared__ float red[10];
    __shared__ float sdef_sh;

    // s_def = wp[i] . default_embed
    float prod = 0.f;
    if (tid < D_DIM) prod = g_wp[i * D_DIM + tid] * defv[tid];
    #pragma unroll
    for (int off = 16; off > 0; off >>= 1)
        prod += __shfl_xor_sync(0xffffffffu, prod, off);
    if ((tid & 31) == 0) red[tid >> 5] = prod;
    __syncthreads();
    if (tid == 0) {
        float s = 0.f;
        #pragma unroll
        for (int w = 0; w < 10; ++w) s += red[w];
        sdef_sh = s;
    }
    __syncthreads();
    const float sdef = sdef_sh;

    float m[SPLITS], l[SPLITS];
    float M = sdef;
    #pragma unroll
    for (int s = 0; s < SPLITS; ++s) {
        m[s] = g_pm[s * N_ROWS + i];
        l[s] = g_pl[s * N_ROWS + i];
        M = fmaxf(M, m[s]);
    }
    float w[SPLITS];
    float edef = fexp(sdef - M);
    float L = edef;
    #pragma unroll
    for (int s = 0; s < SPLITS; ++s) {
        w[s] = fexp(m[s] - M);
        L += l[s] * w[s];
    }
    const float inv = 1.f / L;
    if (tid < D_DIM) {
        float acc = 0.f;
        #pragma unroll
        for (int s = 0; s < SPLITS; ++s)
            acc += g_pacc[(size_t)(s * N_ROWS + i) * DP + tid] * w[s];
        out[i * D_DIM + tid] = acc * inv + (edef * inv) * words[i * D_DIM + tid];
    }
}

// ---------------- launcher ----------------
extern "C" void kernel_launch(void* const* d_in, const int* in_sizes, int n_in,
                              void* d_out, int out_size) {
    const float* words = (const float*)d_in[0];   // [4096, 300]
    const float* vocab = (const float*)d_in[1];   // [50000, 300]
    const float* defv  = (const float*)d_in[2];   // [300]
    const float* W     = (const float*)d_in[3];   // [300, 300]
    float* out = (float*)d_out;                   // [4096, 300]

    cudaFuncSetAttribute(fused_kernel,
                         cudaFuncAttributeMaxDynamicSharedMemorySize, SMEM_BYTES);

    gemm1_kernel<<<N_ROWS / 16, 320>>>(words, W);
    fused_kernel<<<dim3(N_ROWS / BM, SPLITS), 256, SMEM_BYTES>>>(vocab);
    combine_kernel<<<N_ROWS, 320>>>(words, defv, out);
}

// round 9
// speedup vs baseline: 1.1413x; 1.0055x over previous
#include <cuda_runtime.h>
#include <cuda_bf16.h>
#include <math.h>

#define N_ROWS 4096
#define V_SIZE 50000
#define D_DIM  300
#define DP     320    // padded d stride (floats) for value GEMM / g_pacc
#define BM     64
#define BN     64
#define SPLITS 16
#define VC     3136   // vocab rows per split (49 tiles of 64); last split = 2960

typedef unsigned long long u64;

// ---------------- packed f32x2 helpers ----------------
__device__ __forceinline__ u64 pack2(float lo, float hi) {
    u64 r; asm("mov.b64 %0, {%1, %2};" : "=l"(r) : "f"(lo), "f"(hi)); return r;
}
__device__ __forceinline__ u64 fma2(u64 a, u64 b, u64 c) {
    u64 d; asm("fma.rn.f32x2 %0, %1, %2, %3;" : "=l"(d) : "l"(a), "l"(b), "l"(c)); return d;
}
__device__ __forceinline__ u64 add2(u64 a, u64 b) {
    u64 d; asm("add.rn.f32x2 %0, %1, %2;" : "=l"(d) : "l"(a), "l"(b)); return d;
}
__device__ __forceinline__ u64 mul2(u64 a, u64 b) {
    u64 d; asm("mul.rn.f32x2 %0, %1, %2;" : "=l"(d) : "l"(a), "l"(b)); return d;
}

// ---------------- scratch (device globals; no allocation allowed) ----------------
__device__ float g_wp  [N_ROWS * D_DIM];            // words @ W
__device__ float g_pacc[SPLITS * N_ROWS * DP];      // per-split unnormalized sum_j e^{s-m} v_j
__device__ float g_pm  [SPLITS * N_ROWS];           // per-split running max
__device__ float g_pl  [SPLITS * N_ROWS];           // per-split running sum of exp

// ---------------- fast exp (FFMA pipe instead of MUFU) ----------------
__device__ __forceinline__ float fexp(float x) {
    float p = x * 1.4426950408889634f;     // log2(e)
    p = fmaxf(p, -120.0f);                 // 2^-120 ~ 0; also guards -1e30 masks
    float fn = rintf(p);
    float f  = p - fn;                     // f in [-0.5, 0.5]
    float y = 1.3333558146e-3f;
    y = fmaf(y, f, 9.6181291076e-3f);
    y = fmaf(y, f, 5.5504108664e-2f);
    y = fmaf(y, f, 2.4022650695e-1f);
    y = fmaf(y, f, 6.9314718055e-1f);
    y = fmaf(y, f, 1.0f);
    int e = (int)fn;
    float s = __int_as_float((e + 127) << 23);
    return y * s;
}

// ---------------- kernel 1: wp = words @ W ----------------
__global__ __launch_bounds__(320)
void gemm1_kernel(const float* __restrict__ words, const float* __restrict__ W) {
    __shared__ float ws[16 * D_DIM];
    int i0 = blockIdx.x * 16;
    int tid = threadIdx.x;
    for (int t = tid; t < 16 * D_DIM; t += 320)
        ws[t] = words[i0 * D_DIM + t];
    __syncthreads();
    int d = tid;
    if (d < D_DIM) {
        float acc[16];
        #pragma unroll
        for (int r = 0; r < 16; ++r) acc[r] = 0.f;
        for (int k4 = 0; k4 < D_DIM / 4; ++k4) {
            int k = k4 * 4;
            float w0 = W[(k + 0) * D_DIM + d];
            float w1 = W[(k + 1) * D_DIM + d];
            float w2 = W[(k + 2) * D_DIM + d];
            float w3 = W[(k + 3) * D_DIM + d];
            #pragma unroll
            for (int r = 0; r < 16; ++r) {
                float4 wv = *(const float4*)&ws[r * D_DIM + k];
                acc[r] = fmaf(wv.x, w0, acc[r]);
                acc[r] = fmaf(wv.y, w1, acc[r]);
                acc[r] = fmaf(wv.z, w2, acc[r]);
                acc[r] = fmaf(wv.w, w3, acc[r]);
            }
        }
        #pragma unroll
        for (int r = 0; r < 16; ++r)
            g_wp[(i0 + r) * D_DIM + d] = acc[r];
    }
}

// ---------------- kernel 2: fused flash scores+softmax+value (FFMA2) ----------------
// smem floats:
//   wp_sT [300][64]        19200
//   v_s   [64][320]        20480   (row-major vocab tile, zero-padded 300..319)
//   vT_s  [64][68]          4352   (K-chunk transpose; reused as S tile)
//   p2    [64][68] u64      8704   (pre-duplicated (p,p) pairs, [j][i])
//   m/l/al 3*64              192
#define OFF_WP   0
#define OFF_V    (OFF_WP + 300*64)
#define OFF_VT   (OFF_V  + 64*DP)
#define OFF_P2   (OFF_VT + 64*68)        // in floats; u64 region of 64*68 u64
#define OFF_MLA  (OFF_P2 + 64*68*2)
#define SMEM_FLOATS (OFF_MLA + 192)
#define SMEM_BYTES  (SMEM_FLOATS * 4)

__global__ __launch_bounds__(256, 1)
void fused_kernel(const float* __restrict__ vocab) {
    extern __shared__ float sm[];
    float* wp_sT = sm + OFF_WP;
    float* v_s   = sm + OFF_V;
    float* vT_s  = sm + OFF_VT;
    u64*   p2    = (u64*)(sm + OFF_P2);
    float* m_s   = sm + OFF_MLA;
    float* l_s   = m_s + 64;
    float* al_s  = l_s + 64;

    const int tid    = threadIdx.x;
    const int row0   = blockIdx.x * BM;
    const int split  = blockIdx.y;
    const int jbeg   = split * VC;
    const int jend   = min(V_SIZE, jbeg + VC);
    const int ntiles = (jend - jbeg + BN - 1) / BN;

    // score-GEMM mapping: 4 K-groups x 64 positions (8x8 microtile)
    const int kg  = tid >> 6;
    const int pos = tid & 63;
    const int sty = pos >> 3;   // rows sty*8 .. +7
    const int stx = pos & 7;    // cols stx*8 .. +7
    // value-GEMM mapping: 8 row groups x 32 d-lanes, 5 float2 chunks per lane
    const int rg = tid >> 5;    // rows rg*8 .. +7
    const int dc = tid & 31;    // float2 pairs at 2*dc + 64*c, c=0..4 (covers 320 floats)

    // one-time wp tile load (transposed, K-major)
    for (int t = tid; t < BM * D_DIM; t += 256) {
        int i = t & 63;
        int d = t >> 6;
        wp_sT[d * 64 + i] = g_wp[(row0 + i) * D_DIM + d];
    }
    if (tid < 64) { m_s[tid] = -1e30f; l_s[tid] = 0.f; al_s[tid] = 1.f; }

    u64 o2[8][5];
    #pragma unroll
    for (int r = 0; r < 8; ++r)
        #pragma unroll
        for (int c = 0; c < 5; ++c) o2[r][c] = 0ull;

    __syncthreads();

    for (int tile = 0; tile < ntiles; ++tile) {
        const int j0    = jbeg + tile * BN;
        const int valid = min(BN, jend - j0);

        // ---- A: load vocab tile (row-major, zero-padded cols 300..319, OOB rows)
        for (int t = tid; t < 64 * (DP / 4); t += 256) {
            int j = t / (DP / 4);
            int c = t - j * (DP / 4);
            float4 val = make_float4(0.f, 0.f, 0.f, 0.f);
            if (j < valid && c < 75)
                val = ((const float4*)vocab)[(j0 + j) * 75 + c];
            ((float4*)v_s)[j * (DP / 4) + c] = val;
        }
        __syncthreads();

        // ---- B: score GEMM (packed f32x2 along columns), 5 K-chunks w/ transpose staging
        u64 sc2[8][4];
        #pragma unroll
        for (int r = 0; r < 8; ++r)
            #pragma unroll
            for (int c = 0; c < 4; ++c) sc2[r][c] = 0ull;

        for (int ch = 0; ch < 5; ++ch) {
            const int kbase = ch * 64;
            const int klen  = (ch < 4) ? 64 : (D_DIM - 256);  // 44
            for (int t = tid; t < 64 * 64; t += 256) {
                int kk = t & 63;
                int j  = t >> 6;
                if (kk < klen) vT_s[kk * 68 + j] = v_s[j * DP + kbase + kk];
            }
            __syncthreads();
            for (int kk = kg; kk < klen; kk += 4) {
                float4 a0 = *(const float4*)&wp_sT[(kbase + kk) * 64 + sty * 8];
                float4 a1 = *(const float4*)&wp_sT[(kbase + kk) * 64 + sty * 8 + 4];
                float4 b0 = *(const float4*)&vT_s[kk * 68 + stx * 8];
                float4 b1 = *(const float4*)&vT_s[kk * 68 + stx * 8 + 4];
                union { float4 f; u64 u[2]; } ub0, ub1;
                ub0.f = b0; ub1.f = b1;
                u64 bp[4] = {ub0.u[0], ub0.u[1], ub1.u[0], ub1.u[1]};
                float a[8] = {a0.x, a0.y, a0.z, a0.w, a1.x, a1.y, a1.z, a1.w};
                #pragma unroll
                for (int r = 0; r < 8; ++r) {
                    u64 ar = pack2(a[r], a[r]);
                    #pragma unroll
                    for (int c = 0; c < 4; ++c)
                        sc2[r][c] = fma2(ar, bp[c], sc2[r][c]);
                }
            }
            __syncthreads();
        }

        // ---- C: reduce 4 K-group partials into S tile (reuse vT_s), packed adds
        u64* S2 = (u64*)vT_s;   // stride 34 u64 per row
        #pragma unroll 1
        for (int g = 0; g < 4; ++g) {
            if (kg == g) {
                #pragma unroll
                for (int r = 0; r < 8; ++r) {
                    u64* dst = &S2[(sty * 8 + r) * 34 + stx * 4];
                    if (g == 0) {
                        #pragma unroll
                        for (int c = 0; c < 4; ++c) dst[c] = sc2[r][c];
                    } else {
                        #pragma unroll
                        for (int c = 0; c < 4; ++c) dst[c] = add2(dst[c], sc2[r][c]);
                    }
                }
            }
            __syncthreads();
        }

        // ---- D: online softmax update (4 threads per row); store (p,p) pairs
        {
            float* S_s = vT_s;
            const int row = tid >> 2;
            const int q   = tid & 3;
            float sv[16];
            float mloc = -1e30f;
            #pragma unroll
            for (int c = 0; c < 16; ++c) {
                int j = q * 16 + c;
                float s = S_s[row * 68 + j];
                if (j >= valid) s = -1e30f;
                sv[c] = s;
                mloc = fmaxf(mloc, s);
            }
            #pragma unroll
            for (int off = 1; off < 4; off <<= 1)
                mloc = fmaxf(mloc, __shfl_xor_sync(0xffffffffu, mloc, off));
            const float mold = m_s[row];
            const float mnew = fmaxf(mold, mloc);
            float rs = 0.f;
            #pragma unroll
            for (int c = 0; c < 16; ++c) {
                float p = fexp(sv[c] - mnew);
                p2[(q * 16 + c) * 68 + row] = pack2(p, p);
                rs += p;
            }
            #pragma unroll
            for (int off = 1; off < 4; off <<= 1)
                rs += __shfl_xor_sync(0xffffffffu, rs, off);
            if (q == 0) {
                float alpha = fexp(mold - mnew);
                l_s[row]  = l_s[row] * alpha + rs;
                m_s[row]  = mnew;
                al_s[row] = alpha;
            }
        }
        __syncthreads();

        // ---- E: value GEMM accumulate (packed f32x2; rescale then += P @ V_tile)
        {
            #pragma unroll
            for (int r = 0; r < 8; ++r) {
                u64 av = pack2(al_s[rg * 8 + r], al_s[rg * 8 + r]);
                #pragma unroll
                for (int c = 0; c < 5; ++c) o2[r][c] = mul2(o2[r][c], av);
            }

            #pragma unroll 2
            for (int j = 0; j < 64; ++j) {
                const u64* pj = &p2[j * 68 + rg * 8];
                ulonglong2 pA = *(const ulonglong2*)(pj + 0);
                ulonglong2 pB = *(const ulonglong2*)(pj + 2);
                ulonglong2 pC = *(const ulonglong2*)(pj + 4);
                ulonglong2 pD = *(const ulonglong2*)(pj + 6);
                u64 pr[8] = {pA.x, pA.y, pB.x, pB.y, pC.x, pC.y, pD.x, pD.y};
                u64 vv[5];
                #pragma unroll
                for (int c = 0; c < 5; ++c)
                    vv[c] = *(const u64*)&v_s[j * DP + 2 * dc + 64 * c];
                #pragma unroll
                for (int r = 0; r < 8; ++r)
                    #pragma unroll
                    for (int c = 0; c < 5; ++c)
                        o2[r][c] = fma2(pr[r], vv[c], o2[r][c]);
            }
        }
        __syncthreads();
    }

    // ---- F: write split partials (packed stores)
    {
        const int base = split * N_ROWS + row0;
        #pragma unroll
        for (int r = 0; r < 8; ++r) {
            float* dst = &g_pacc[(size_t)(base + rg * 8 + r) * DP];
            #pragma unroll
            for (int c = 0; c < 5; ++c)
                *(u64*)&dst[2 * dc + 64 * c] = o2[r][c];
        }
        if (tid < 64) {
            g_pm[split * N_ROWS + row0 + tid] = m_s[tid];
            g_pl[split * N_ROWS + row0 + tid] = l_s[tid];
        }
    }
}

// ---------------- kernel 3: combine splits + default-embed column ----------------
__global__ __launch_bounds__(320)
void combine_kernel(const float* __restrict__ words,
                    const float* __restrict__ defv,
                    float* __restrict__ out) {
    const int i   = blockIdx.x;
    const int tid = threadIdx.x;
    __shared__ float red[10];
    __shared__ float sdef_sh;

    // s_def = wp[i] . default_embed
    float prod = 0.f;
    if (tid < D_DIM) prod = g_wp[i * D_DIM + tid] * defv[tid];
    #pragma unroll
    for (int off = 16; off > 0; off >>= 1)
        prod += __shfl_xor_sync(0xffffffffu, prod, off);
    if ((tid & 31) == 0) red[tid >> 5] = prod;
    __syncthreads();
    if (tid == 0) {
        float s = 0.f;
        #pragma unroll
        for (int w = 0; w < 10; ++w) s += red[w];
        sdef_sh = s;
    }
    __syncthreads();
    const float sdef = sdef_sh;

    float m[SPLITS], l[SPLITS];
    float M = sdef;
    #pragma unroll
    for (int s = 0; s < SPLITS; ++s) {
        m[s] = g_pm[s * N_ROWS + i];
        l[s] = g_pl[s * N_ROWS + i];
        M = fmaxf(M, m[s]);
    }
    float w[SPLITS];
    float edef = fexp(sdef - M);
    float L = edef;
    #pragma unroll
    for (int s = 0; s < SPLITS; ++s) {
        w[s] = fexp(m[s] - M);
        L += l[s] * w[s];
    }
    const float inv = 1.f / L;
    if (tid < D_DIM) {
        float acc = 0.f;
        #pragma unroll
        for (int s = 0; s < SPLITS; ++s)
            acc += g_pacc[(size_t)(s * N_ROWS + i) * DP + tid] * w[s];
        out[i * D_DIM + tid] = acc * inv + (edef * inv) * words[i * D_DIM + tid];
    }
}

// ---------------- launcher ----------------
extern "C" void kernel_launch(void* const* d_in, const int* in_sizes, int n_in,
                              void* d_out, int out_size) {
    const float* words = (const float*)d_in[0];   // [4096, 300]
    const float* vocab = (const float*)d_in[1];   // [50000, 300]
    const float* defv  = (const float*)d_in[2];   // [300]
    const float* W     = (const float*)d_in[3];   // [300, 300]
    float* out = (float*)d_out;                   // [4096, 300]

    cudaFuncSetAttribute(fused_kernel,
                         cudaFuncAttributeMaxDynamicSharedMemorySize, SMEM_BYTES);

    gemm1_kernel<<<N_ROWS / 16, 320>>>(words, W);
    fused_kernel<<<dim3(N_ROWS / BM, SPLITS), 256, SMEM_BYTES>>>(vocab);
    combine_kernel<<<N_ROWS, 320>>>(words, defv, out);
}